// round 8
// baseline (speedup 1.0000x reference)
#include <cuda_runtime.h>

// Precontracted weight matrix T[o][i], alpha folded in (O<=1024).
__device__ float g_T[8192];
// Handshake counters: zero at module load; kernel restores them to zero
// before exiting, so every graph replay sees the same initial state.
__device__ unsigned g_done = 0;
__device__ unsigned g_exit = 0;

// Compile-time Cayley contraction table for Cl(3,0):
// CIJ[i][j] = reorder_sign(i,j) * sigma(i^j), sigma = sign of e_k e_k.
// Derivation: reorder parity for a in {0,1}:0, {2,3}:j0, {4,5}:j0^j1, {6,7}:j1;
// sigma = [+,+,+,-,+,-,-,-].
__device__ __forceinline__ void gp_accum(float acc[8],
                                         const float win[8],
                                         const float wout[8])
{
    constexpr float CIJ[8][8] = {
        { 1.f, 1.f, 1.f,-1.f, 1.f,-1.f,-1.f,-1.f},
        { 1.f, 1.f,-1.f, 1.f,-1.f, 1.f,-1.f,-1.f},
        { 1.f, 1.f, 1.f,-1.f,-1.f, 1.f, 1.f, 1.f},
        {-1.f,-1.f, 1.f,-1.f,-1.f, 1.f,-1.f,-1.f},
        { 1.f, 1.f, 1.f,-1.f, 1.f,-1.f,-1.f,-1.f},
        {-1.f,-1.f, 1.f,-1.f, 1.f,-1.f, 1.f, 1.f},
        {-1.f,-1.f,-1.f, 1.f, 1.f,-1.f,-1.f,-1.f},
        {-1.f,-1.f, 1.f,-1.f,-1.f, 1.f,-1.f,-1.f},
    };
    #pragma unroll
    for (int i = 0; i < 8; i++) {
        float s = acc[i];
        #pragma unroll
        for (int j = 0; j < 8; j++)
            s += CIJ[i][j] * win[j] * wout[i ^ j];   // sign folds into FFMA
        acc[i] = s;
    }
}

// Fused single-launch kernel for O==128, B%128==0.
// Grid = 128 blocks x 512 threads; all blocks co-resident (<=152 SMs).
// Block bid: (1) produces T[bid,:], (2) consumes B/128 batch rows.
#define FUSED_BLOCKS 128
__global__ __launch_bounds__(512)
void fused_kernel(const float* __restrict__ x,
                  const float* __restrict__ W_in,
                  const float* __restrict__ W_out,
                  float* __restrict__ out,
                  int H, int rowsPerBlock, float alpha)
{
    __shared__ float Ts[32 * 33];        // 32 o-groups x 32 floats, stride 33
    __shared__ float xs[32 * 9];         // up to 32 rows x 8 (+pad)
    __shared__ float red[16][8];

    const int tid = threadIdx.x;
    const int o = blockIdx.x;
    const int b0 = blockIdx.x * rowsPerBlock;

    // ---- stage x early (independent of producer chain) ----
    const int nxvec = rowsPerBlock * 2;  // float4s
    if (tid < nxvec) {
        float4 g = *((const float4*)(x + (size_t)b0 * 8) + tid);
        const float v[4] = {g.x, g.y, g.z, g.w};
        #pragma unroll
        for (int e = 0; e < 4; e++) {
            int idx = tid * 4 + e;       // row = idx>>3, col = idx&7
            xs[(idx >> 3) * 9 + (idx & 7)] = v[e];
        }
    }

    // ---- produce T[o,:] ----
    {
        float acc[8];
        #pragma unroll
        for (int i = 0; i < 8; i++) acc[i] = 0.0f;

        const float* woutBase = W_out + (size_t)o * H * 8;
        for (int h = tid; h < H; h += 512) {
            float4 a0 = *(const float4*)(W_in + h * 8);
            float4 a1 = *(const float4*)(W_in + h * 8 + 4);
            float4 b0v = *(const float4*)(woutBase + h * 8);
            float4 b1v = *(const float4*)(woutBase + h * 8 + 4);
            float win[8]  = {a0.x, a0.y, a0.z, a0.w, a1.x, a1.y, a1.z, a1.w};
            float wout[8] = {b0v.x, b0v.y, b0v.z, b0v.w, b1v.x, b1v.y, b1v.z, b1v.w};
            gp_accum(acc, win, wout);
        }
        #pragma unroll
        for (int i = 0; i < 8; i++)
            #pragma unroll
            for (int off = 16; off > 0; off >>= 1)
                acc[i] += __shfl_xor_sync(0xffffffff, acc[i], off);

        const int lane = tid & 31, w = tid >> 5;
        if (lane == 0) {
            #pragma unroll
            for (int i = 0; i < 8; i++) red[w][i] = acc[i];
        }
        __syncthreads();
        if (tid < 8) {
            float s = 0.0f;
            #pragma unroll
            for (int ww = 0; ww < 16; ww++) s += red[ww][tid];
            g_T[o * 8 + tid] = alpha * s;
        }
        __threadfence();   // release g_T stores
        __syncthreads();
        if (tid == 0) atomicAdd(&g_done, 1u);
    }

    // ---- wait for all producers ----
    if (tid == 0) {
        while (*(volatile unsigned*)&g_done < (unsigned)FUSED_BLOCKS) { }
    }
    __syncthreads();
    __threadfence();       // acquire: order g_T loads after flag observation

    // ---- stage T into shared (vectorized, conflict-free) ----
    if (tid < 256) {
        float4 g = *((const float4*)g_T + tid);   // 1024 floats
        const float v[4] = {g.x, g.y, g.z, g.w};
        #pragma unroll
        for (int e = 0; e < 4; e++) {
            int idx = tid * 4 + e;
            Ts[(idx >> 5) * 33 + (idx & 31)] = v[e];
        }
    }
    __syncthreads();

    // ---- consume: rowsPerBlock rows, 512 threads ----
    const int og = tid & 31;
    const int bq = tid >> 5;   // 0..15

    float t[32];
    #pragma unroll
    for (int k = 0; k < 32; k++) t[k] = Ts[og * 33 + k];   // conflict-free

    for (int bl = bq; bl < rowsPerBlock; bl += 16) {
        float xv[8];
        #pragma unroll
        for (int i = 0; i < 8; i++) xv[i] = xs[bl * 9 + i];  // warp broadcast

        float s0 = 0, s1 = 0, s2 = 0, s3 = 0;
        #pragma unroll
        for (int i = 0; i < 8; i++) {
            s0 += xv[i] * t[i];
            s1 += xv[i] * t[8 + i];
            s2 += xv[i] * t[16 + i];
            s3 += xv[i] * t[24 + i];
        }
        float4 o4 = {s0, s1, s2, s3};
        *(float4*)(out + (size_t)(b0 + bl) * 128 + og * 4) = o4;
    }

    // ---- reset handshake for the next replay (last block out) ----
    __syncthreads();
    if (tid == 0) {
        unsigned prev = atomicAdd(&g_exit, 1u);
        if (prev == FUSED_BLOCKS - 1) {
            g_done = 0;
            g_exit = 0;
            __threadfence();
        }
    }
}

// ---------- generic two-kernel fallback (any O/H/B) ----------
__global__ void compute_T_generic(const float* __restrict__ W_in,
                                  const float* __restrict__ W_out,
                                  int H, float alpha)
{
    const int o = blockIdx.x;
    const int tid = threadIdx.x;
    float acc[8];
    #pragma unroll
    for (int i = 0; i < 8; i++) acc[i] = 0.0f;
    const float* woutBase = W_out + (size_t)o * H * 8;
    for (int h = tid; h < H; h += blockDim.x) {
        float4 a0 = *(const float4*)(W_in + h * 8);
        float4 a1 = *(const float4*)(W_in + h * 8 + 4);
        float4 b0 = *(const float4*)(woutBase + h * 8);
        float4 b1 = *(const float4*)(woutBase + h * 8 + 4);
        float win[8]  = {a0.x, a0.y, a0.z, a0.w, a1.x, a1.y, a1.z, a1.w};
        float wout[8] = {b0.x, b0.y, b0.z, b0.w, b1.x, b1.y, b1.z, b1.w};
        gp_accum(acc, win, wout);
    }
    #pragma unroll
    for (int i = 0; i < 8; i++)
        #pragma unroll
        for (int off = 16; off > 0; off >>= 1)
            acc[i] += __shfl_xor_sync(0xffffffff, acc[i], off);
    __shared__ float red[8][8];
    const int lane = tid & 31, w = tid >> 5;
    const int nw = blockDim.x >> 5;
    if (lane == 0) {
        #pragma unroll
        for (int i = 0; i < 8; i++) red[w][i] = acc[i];
    }
    __syncthreads();
    if (tid < 8) {
        float s = 0.0f;
        for (int ww = 0; ww < nw; ww++) s += red[ww][tid];
        g_T[o * 8 + tid] = alpha * s;
    }
}

__global__ void finalize_generic_kernel(const float* __restrict__ x,
                                        float* __restrict__ out, int O)
{
    extern __shared__ float Tg[];  // [8][O] transposed
    for (int idx = threadIdx.x; idx < O * 8; idx += blockDim.x) {
        int o = idx >> 3, i = idx & 7;
        Tg[i * O + o] = g_T[idx];
    }
    __syncthreads();
    const int b = blockIdx.x;
    float4 x0 = *(const float4*)(x + b * 8);
    float4 x1 = *(const float4*)(x + b * 8 + 4);
    for (int o = threadIdx.x; o < O; o += blockDim.x) {
        float s = x0.x * Tg[o]         + x0.y * Tg[O + o]
                + x0.z * Tg[2 * O + o] + x0.w * Tg[3 * O + o]
                + x1.x * Tg[4 * O + o] + x1.y * Tg[5 * O + o]
                + x1.z * Tg[6 * O + o] + x1.w * Tg[7 * O + o];
        out[(size_t)b * O + o] = s;
    }
}

extern "C" void kernel_launch(void* const* d_in, const int* in_sizes, int n_in,
                              void* d_out, int out_size)
{
    const float* x     = (const float*)d_in[0];  // [B,8]
    const float* W_in  = (const float*)d_in[1];  // [H,1,8]
    const float* W_out = (const float*)d_in[2];  // [O,H,8]

    const int B = in_sizes[0] / 8;
    const int H = in_sizes[1] / 8;
    const int O = in_sizes[2] / (H * 8);

    // alpha = 1 - (1-dt)^n_free, dt=0.1, n_free=10
    double p = 1.0;
    for (int i = 0; i < 10; i++) p *= 0.9;
    const float alpha = (float)(1.0 - p);

    const int rowsPerBlock = B / FUSED_BLOCKS;
    if (O == FUSED_BLOCKS && (B % FUSED_BLOCKS) == 0 &&
        rowsPerBlock >= 16 && rowsPerBlock <= 32 && (rowsPerBlock % 16) == 0) {
        fused_kernel<<<FUSED_BLOCKS, 512>>>(x, W_in, W_out, (float*)d_out,
                                            H, rowsPerBlock, alpha);
    } else {
        compute_T_generic<<<O, 256>>>(W_in, W_out, H, alpha);
        finalize_generic_kernel<<<B, 128, O * 8 * sizeof(float)>>>(x, (float*)d_out, O);
    }
}

// round 9
// speedup vs baseline: 1.0370x; 1.0370x over previous
#include <cuda_runtime.h>

// ---------------- generic fallback state ----------------
__device__ float g_T[8192];

// Compile-time Cayley contraction table for Cl(3,0):
// CIJ[i][j] = reorder_sign(i,j) * sigma(i^j)
__device__ __forceinline__ constexpr float cij_const(int i, int j) {
    constexpr float CIJ[8][8] = {
        { 1.f, 1.f, 1.f,-1.f, 1.f,-1.f,-1.f,-1.f},
        { 1.f, 1.f,-1.f, 1.f,-1.f, 1.f,-1.f,-1.f},
        { 1.f, 1.f, 1.f,-1.f,-1.f, 1.f, 1.f, 1.f},
        {-1.f,-1.f, 1.f,-1.f,-1.f, 1.f,-1.f,-1.f},
        { 1.f, 1.f, 1.f,-1.f, 1.f,-1.f,-1.f,-1.f},
        {-1.f,-1.f, 1.f,-1.f, 1.f,-1.f, 1.f, 1.f},
        {-1.f,-1.f,-1.f, 1.f, 1.f,-1.f,-1.f,-1.f},
        {-1.f,-1.f, 1.f,-1.f,-1.f, 1.f,-1.f,-1.f},
    };
    return CIJ[i][j];
}

__device__ __forceinline__ int bitrev5(int v) {
    return ((v & 1) << 4) | ((v & 2) << 2) | (v & 4) | ((v & 8) >> 2) | ((v & 16) >> 4);
}

// ---------------- fused tile kernel (O==128) ----------------
// Grid = 128 blocks = 32 o-tiles x 4 b-tiles, 512 threads.
// Block (ot, bt): computes T[ot*4+c][i] locally (no cross-block dependency),
// then writes out[bt*B/4 .. , ot*4 .. ot*4+3].
__global__ __launch_bounds__(512)
void tile_kernel(const float* __restrict__ x,
                 const float* __restrict__ W_in,
                 const float* __restrict__ W_out,
                 float* __restrict__ out,
                 int H, int rowsPerBlock, float alpha)
{
    __shared__ float red2[16][32];   // [warp][value]
    __shared__ float Tf[32];         // final T slice: [c*8+i]

    const int tid  = threadIdx.x;
    const int lane = tid & 31;
    const int w    = tid >> 5;
    const int ot = blockIdx.x >> 2;          // 0..31
    const int bt = blockIdx.x & 3;           // 0..3
    const int o0 = ot * 4;
    const int b0 = bt * rowsPerBlock;

    // ---- produce T[o0..o0+3][0..7] : vals[c*8+i] ----
    float vals[32];
    #pragma unroll
    for (int k = 0; k < 32; k++) vals[k] = 0.0f;

    for (int h = tid; h < H; h += 512) {
        float4 a0 = *(const float4*)(W_in + h * 8);
        float4 a1 = *(const float4*)(W_in + h * 8 + 4);
        float win[8] = {a0.x, a0.y, a0.z, a0.w, a1.x, a1.y, a1.z, a1.w};
        #pragma unroll
        for (int c = 0; c < 4; c++) {
            const float* wp = W_out + ((size_t)(o0 + c) * H + h) * 8;
            float4 b0v = *(const float4*)(wp);
            float4 b1v = *(const float4*)(wp + 4);
            float wo[8] = {b0v.x, b0v.y, b0v.z, b0v.w, b1v.x, b1v.y, b1v.z, b1v.w};
            #pragma unroll
            for (int i = 0; i < 8; i++) {
                float s = vals[c * 8 + i];
                #pragma unroll
                for (int j = 0; j < 8; j++) {
                    // constexpr sign folds into FFMA negate modifier
                    s = fmaf(cij_const(i, j) > 0.f ? win[j] : -win[j],
                             wo[i ^ j], s);
                }
                vals[c * 8 + i] = s;
            }
        }
    }

    // ---- butterfly reduce 32 values across 32 lanes ----
    // After 5 rounds, lane l holds the lane-sum of value index bitrev5(l).
    {
        int m = 16;
        #pragma unroll
        for (int r = 0; r < 5; r++) {
            const int bit = (lane >> r) & 1;
            #pragma unroll
            for (int k = 0; k < m; k++) {
                float keep = bit ? vals[k + m] : vals[k];
                float send = bit ? vals[k]     : vals[k + m];
                float recv = __shfl_xor_sync(0xffffffff, send, 1 << r);
                vals[k] = keep + recv;
            }
            m >>= 1;
        }
    }
    red2[w][lane] = vals[0];
    __syncthreads();
    if (tid < 32) {
        float s = 0.0f;
        #pragma unroll
        for (int ww = 0; ww < 16; ww++) s += red2[ww][tid];
        Tf[bitrev5(tid)] = alpha * s;
    }
    __syncthreads();

    // ---- consume: rowsPerBlock rows, 4 outputs each ----
    float tT[32];
    #pragma unroll
    for (int k = 0; k < 32; k++) tT[k] = Tf[k];   // broadcast LDS

    for (int row = tid; row < rowsPerBlock; row += 512) {
        const float* xp = x + (size_t)(b0 + row) * 8;
        float4 xa = *(const float4*)xp;
        float4 xb = *(const float4*)(xp + 4);
        float xv[8] = {xa.x, xa.y, xa.z, xa.w, xb.x, xb.y, xb.z, xb.w};

        float4 r4;
        float s0 = 0, s1 = 0, s2 = 0, s3 = 0;
        #pragma unroll
        for (int i = 0; i < 8; i++) {
            s0 = fmaf(xv[i], tT[i],      s0);
            s1 = fmaf(xv[i], tT[8 + i],  s1);
            s2 = fmaf(xv[i], tT[16 + i], s2);
            s3 = fmaf(xv[i], tT[24 + i], s3);
        }
        r4.x = s0; r4.y = s1; r4.z = s2; r4.w = s3;
        *(float4*)(out + (size_t)(b0 + row) * 128 + o0) = r4;
    }
}

// ---------------- generic two-kernel fallback (any O/H/B) ----------------
__device__ __forceinline__ void gp_accum(float acc[8],
                                         const float win[8],
                                         const float wout[8])
{
    #pragma unroll
    for (int i = 0; i < 8; i++) {
        float s = acc[i];
        #pragma unroll
        for (int j = 0; j < 8; j++)
            s = fmaf(cij_const(i, j) > 0.f ? win[j] : -win[j], wout[i ^ j], s);
        acc[i] = s;
    }
}

__global__ void compute_T_generic(const float* __restrict__ W_in,
                                  const float* __restrict__ W_out,
                                  int H, float alpha)
{
    const int o = blockIdx.x;
    const int tid = threadIdx.x;
    float acc[8];
    #pragma unroll
    for (int i = 0; i < 8; i++) acc[i] = 0.0f;
    const float* woutBase = W_out + (size_t)o * H * 8;
    for (int h = tid; h < H; h += blockDim.x) {
        float4 a0 = *(const float4*)(W_in + h * 8);
        float4 a1 = *(const float4*)(W_in + h * 8 + 4);
        float4 b0 = *(const float4*)(woutBase + h * 8);
        float4 b1 = *(const float4*)(woutBase + h * 8 + 4);
        float win[8]  = {a0.x, a0.y, a0.z, a0.w, a1.x, a1.y, a1.z, a1.w};
        float wout[8] = {b0.x, b0.y, b0.z, b0.w, b1.x, b1.y, b1.z, b1.w};
        gp_accum(acc, win, wout);
    }
    #pragma unroll
    for (int i = 0; i < 8; i++)
        #pragma unroll
        for (int off = 16; off > 0; off >>= 1)
            acc[i] += __shfl_xor_sync(0xffffffff, acc[i], off);
    __shared__ float red[8][8];
    const int lane = tid & 31, w = tid >> 5;
    const int nw = blockDim.x >> 5;
    if (lane == 0) {
        #pragma unroll
        for (int i = 0; i < 8; i++) red[w][i] = acc[i];
    }
    __syncthreads();
    if (tid < 8) {
        float s = 0.0f;
        for (int ww = 0; ww < nw; ww++) s += red[ww][tid];
        g_T[o * 8 + tid] = alpha * s;
    }
}

__global__ void finalize_generic_kernel(const float* __restrict__ x,
                                        float* __restrict__ out, int O)
{
    extern __shared__ float Tg[];  // [8][O] transposed
    for (int idx = threadIdx.x; idx < O * 8; idx += blockDim.x) {
        int o = idx >> 3, i = idx & 7;
        Tg[i * O + o] = g_T[idx];
    }
    __syncthreads();
    const int b = blockIdx.x;
    float4 x0 = *(const float4*)(x + b * 8);
    float4 x1 = *(const float4*)(x + b * 8 + 4);
    for (int o = threadIdx.x; o < O; o += blockDim.x) {
        float s = x0.x * Tg[o]         + x0.y * Tg[O + o]
                + x0.z * Tg[2 * O + o] + x0.w * Tg[3 * O + o]
                + x1.x * Tg[4 * O + o] + x1.y * Tg[5 * O + o]
                + x1.z * Tg[6 * O + o] + x1.w * Tg[7 * O + o];
        out[(size_t)b * O + o] = s;
    }
}

extern "C" void kernel_launch(void* const* d_in, const int* in_sizes, int n_in,
                              void* d_out, int out_size)
{
    const float* x     = (const float*)d_in[0];  // [B,8]
    const float* W_in  = (const float*)d_in[1];  // [H,1,8]
    const float* W_out = (const float*)d_in[2];  // [O,H,8]

    const int B = in_sizes[0] / 8;
    const int H = in_sizes[1] / 8;
    const int O = in_sizes[2] / (H * 8);

    // alpha = 1 - (1-dt)^n_free, dt=0.1, n_free=10
    double p = 1.0;
    for (int i = 0; i < 10; i++) p *= 0.9;
    const float alpha = (float)(1.0 - p);

    if (O == 128 && (B % 4) == 0) {
        const int rowsPerBlock = B / 4;
        tile_kernel<<<128, 512>>>(x, W_in, W_out, (float*)d_out,
                                  H, rowsPerBlock, alpha);
    } else {
        compute_T_generic<<<O, 256>>>(W_in, W_out, H, alpha);
        finalize_generic_kernel<<<B, 128, O * 8 * sizeof(float)>>>(x, (float*)d_out, O);
    }
}